// round 1
// baseline (speedup 1.0000x reference)
#include <cuda_runtime.h>
#include <math.h>

#define Bz  4
#define Tt  2048
#define STt 2048
#define Cc  1024
#define Hh  16
#define Dd  64
#define MROWS (Bz * STt)   // 8192

// Scratch (static __device__ arrays: allocation-guard-safe)
__device__ float g_q[(size_t)Bz * STt * Cc];
__device__ float g_k[(size_t)Bz * Tt  * Cc];
__device__ float g_v[(size_t)Bz * Tt  * Cc];
__device__ float g_y[(size_t)Bz * STt * Cc];

// ---------------------------------------------------------------------------
// Out[M,N] = A[M,K] @ W[N,K]^T   (torch Linear convention, all row-major fp32)
// 128x128x8 tiles, 256 threads, 8x8 per-thread microtile (2x2 of 4x4 strips)
// ---------------------------------------------------------------------------
__global__ __launch_bounds__(256, 2)
void sgemm_tn(const float* __restrict__ A, const float* __restrict__ W,
              float* __restrict__ Out, int M, int N, int K)
{
    __shared__ float As[8][128];   // [k][m] transposed stage
    __shared__ float Ws[8][128];   // [k][n] transposed stage

    const int tid = threadIdx.x;
    const int tx  = tid & 15;      // 0..15 -> n strips
    const int ty  = tid >> 4;      // 0..15 -> m strips
    const int m0  = blockIdx.y * 128;
    const int n0  = blockIdx.x * 128;

    const int lr = tid >> 1;            // 0..127 row within tile
    const int lk = (tid & 1) * 4;       // 0 or 4

    const float* Ap = A + (size_t)(m0 + lr) * K + lk;
    const float* Wp = W + (size_t)(n0 + lr) * K + lk;

    float acc[8][8];
    #pragma unroll
    for (int i = 0; i < 8; i++)
        #pragma unroll
        for (int j = 0; j < 8; j++) acc[i][j] = 0.f;

    float4 av = *(const float4*)(Ap);
    float4 wv = *(const float4*)(Wp);

    for (int k0 = 0; k0 < K; k0 += 8) {
        __syncthreads();
        As[lk + 0][lr] = av.x; As[lk + 1][lr] = av.y;
        As[lk + 2][lr] = av.z; As[lk + 3][lr] = av.w;
        Ws[lk + 0][lr] = wv.x; Ws[lk + 1][lr] = wv.y;
        Ws[lk + 2][lr] = wv.z; Ws[lk + 3][lr] = wv.w;
        __syncthreads();

        if (k0 + 8 < K) {   // prefetch next tile into regs, overlap with FMAs
            av = *(const float4*)(Ap + k0 + 8);
            wv = *(const float4*)(Wp + k0 + 8);
        }

        #pragma unroll
        for (int kk = 0; kk < 8; kk++) {
            float a[8], w[8];
            *(float4*)&a[0] = *(const float4*)&As[kk][ty * 4];
            *(float4*)&a[4] = *(const float4*)&As[kk][64 + ty * 4];
            *(float4*)&w[0] = *(const float4*)&Ws[kk][tx * 4];
            *(float4*)&w[4] = *(const float4*)&Ws[kk][64 + tx * 4];
            #pragma unroll
            for (int i = 0; i < 8; i++)
                #pragma unroll
                for (int j = 0; j < 8; j++)
                    acc[i][j] += a[i] * w[j];
        }
    }

    #pragma unroll
    for (int i = 0; i < 8; i++) {
        const int r = m0 + ((i < 4) ? (ty * 4 + i) : (64 + ty * 4 + (i - 4)));
        float* op = Out + (size_t)r * N + n0;
        *(float4*)(op + tx * 4)      = make_float4(acc[i][0], acc[i][1], acc[i][2], acc[i][3]);
        *(float4*)(op + 64 + tx * 4) = make_float4(acc[i][4], acc[i][5], acc[i][6], acc[i][7]);
    }
}

// ---------------------------------------------------------------------------
// Flash attention, no masking, no 1/sqrt(D) scale. D = 64.
// Block: 64 q rows x one head. 256 threads = 16x16 microtile grid (4x4 each).
// Smem: Qs/Ks padded to 65 floats/row (scalar access), Vs/Ps padded to 68
// (16B-aligned rows -> float4 access).
// ---------------------------------------------------------------------------
#define SM_Q 0
#define SM_K (64 * 65)
#define SM_V (2 * 64 * 65)
#define SM_P (2 * 64 * 65 + 64 * 68)
#define SMEM_FLOATS (2 * 64 * 65 + 2 * 64 * 68)

__global__ __launch_bounds__(256, 2)
void flash_attn(const float* __restrict__ q, const float* __restrict__ k,
                const float* __restrict__ v, float* __restrict__ y)
{
    extern __shared__ float sm[];
    float* Qs = sm + SM_Q;
    float* Ks = sm + SM_K;
    float* Vs = sm + SM_V;
    float* Ps = sm + SM_P;

    const int tid = threadIdx.x;
    const int tx  = tid & 15;
    const int ty  = tid >> 4;
    const int i0  = blockIdx.x * 64;
    const int h   = blockIdx.y;
    const int b   = blockIdx.z;

    const float* qb = q + ((size_t)b * STt + i0) * Cc + h * Dd;
    const float* kb = k + (size_t)b * Tt * Cc + h * Dd;
    const float* vb = v + (size_t)b * Tt * Cc + h * Dd;

    const int ld = tid & 15;   // d4 group (coalesced over lanes)
    const int lr = tid >> 4;   // row 0..15

    // Load Q tile [64][64] into Qs (rows padded to 65)
    #pragma unroll
    for (int g = 0; g < 4; g++) {
        const int i = lr + g * 16;
        float4 t4 = *(const float4*)(qb + (size_t)i * Cc + ld * 4);
        float* dst = Qs + i * 65 + ld * 4;
        dst[0] = t4.x; dst[1] = t4.y; dst[2] = t4.z; dst[3] = t4.w;
    }

    float m[4], l[4], o[4][4];
    #pragma unroll
    for (int ii = 0; ii < 4; ii++) {
        m[ii] = -1e30f; l[ii] = 0.f;
        #pragma unroll
        for (int cc = 0; cc < 4; cc++) o[ii][cc] = 0.f;
    }

    for (int jt = 0; jt < Tt / 64; jt++) {
        __syncthreads();   // protect Vs (read in prev PV) and Ks
        #pragma unroll
        for (int g = 0; g < 4; g++) {
            const int j = lr + g * 16;
            const size_t go = (size_t)(jt * 64 + j) * Cc + ld * 4;
            float4 k4 = *(const float4*)(kb + go);
            float* kd = Ks + j * 65 + ld * 4;
            kd[0] = k4.x; kd[1] = k4.y; kd[2] = k4.z; kd[3] = k4.w;
            float4 v4 = *(const float4*)(vb + go);
            *(float4*)(Vs + j * 68 + ld * 4) = v4;
        }
        __syncthreads();

        // S = Q @ K^T fragment (4x4 per thread)
        float s[4][4];
        #pragma unroll
        for (int ii = 0; ii < 4; ii++)
            #pragma unroll
            for (int jj = 0; jj < 4; jj++) s[ii][jj] = 0.f;

        const float* qrow = Qs + (ty * 4) * 65;
        const float* krow = Ks + (tx * 4) * 65;
        #pragma unroll 4
        for (int d = 0; d < 64; d++) {
            float qf[4], kf[4];
            #pragma unroll
            for (int ii = 0; ii < 4; ii++) qf[ii] = qrow[ii * 65 + d];
            #pragma unroll
            for (int jj = 0; jj < 4; jj++) kf[jj] = krow[jj * 65 + d];
            #pragma unroll
            for (int ii = 0; ii < 4; ii++)
                #pragma unroll
                for (int jj = 0; jj < 4; jj++)
                    s[ii][jj] += qf[ii] * kf[jj];
        }

        // Online softmax: row stats live in 16 tx lanes (xor-shuffle width 16)
        #pragma unroll
        for (int ii = 0; ii < 4; ii++) {
            float mm = fmaxf(fmaxf(s[ii][0], s[ii][1]), fmaxf(s[ii][2], s[ii][3]));
            #pragma unroll
            for (int off = 8; off; off >>= 1)
                mm = fmaxf(mm, __shfl_xor_sync(0xffffffffu, mm, off));
            const float mn = fmaxf(m[ii], mm);
            const float sc = __expf(m[ii] - mn);
            m[ii] = mn;
            float ss = 0.f;
            #pragma unroll
            for (int jj = 0; jj < 4; jj++) {
                s[ii][jj] = __expf(s[ii][jj] - mn);
                ss += s[ii][jj];
            }
            #pragma unroll
            for (int off = 8; off; off >>= 1)
                ss += __shfl_xor_sync(0xffffffffu, ss, off);
            l[ii] = l[ii] * sc + ss;
            #pragma unroll
            for (int cc = 0; cc < 4; cc++) o[ii][cc] *= sc;
            *(float4*)(Ps + (ty * 4 + ii) * 68 + tx * 4) =
                make_float4(s[ii][0], s[ii][1], s[ii][2], s[ii][3]);
        }
        __syncthreads();   // Ps visible to all

        // O += P @ V (same 4x4 microtile; P scalar broadcast, V float4)
        const float* prow = Ps + (ty * 4) * 68;
        #pragma unroll 4
        for (int j = 0; j < 64; j++) {
            float pv[4];
            #pragma unroll
            for (int ii = 0; ii < 4; ii++) pv[ii] = prow[ii * 68 + j];
            float4 v4 = *(const float4*)(Vs + j * 68 + tx * 4);
            #pragma unroll
            for (int ii = 0; ii < 4; ii++) {
                o[ii][0] += pv[ii] * v4.x;
                o[ii][1] += pv[ii] * v4.y;
                o[ii][2] += pv[ii] * v4.z;
                o[ii][3] += pv[ii] * v4.w;
            }
        }
    }

    // Normalize and store y[b, row, h*64 + c]
    #pragma unroll
    for (int ii = 0; ii < 4; ii++) {
        const float inv = 1.0f / l[ii];
        const int row = i0 + ty * 4 + ii;
        float4 r4 = make_float4(o[ii][0] * inv, o[ii][1] * inv,
                                o[ii][2] * inv, o[ii][3] * inv);
        *(float4*)(y + ((size_t)b * STt + row) * Cc + h * Dd + tx * 4) = r4;
    }
}

// ---------------------------------------------------------------------------
extern "C" void kernel_launch(void* const* d_in, const int* in_sizes, int n_in,
                              void* d_out, int out_size)
{
    const float* x  = (const float*)d_in[0];
    const float* sx = (const float*)d_in[1];
    const float* Wq = (const float*)d_in[2];
    const float* Wk = (const float*)d_in[3];
    const float* Wv = (const float*)d_in[4];
    const float* Wc = (const float*)d_in[5];
    float* out = (float*)d_out;

    float *qb, *kb, *vb, *yb;
    cudaGetSymbolAddress((void**)&qb, g_q);
    cudaGetSymbolAddress((void**)&kb, g_k);
    cudaGetSymbolAddress((void**)&vb, g_v);
    cudaGetSymbolAddress((void**)&yb, g_y);

    const int smem = SMEM_FLOATS * (int)sizeof(float);   // 68096 B
    cudaFuncSetAttribute(flash_attn, cudaFuncAttributeMaxDynamicSharedMemorySize, smem);

    dim3 gg(Cc / 128, MROWS / 128);   // (8, 64)

    sgemm_tn<<<gg, 256>>>(sx, Wq, qb, MROWS, Cc, Cc);
    sgemm_tn<<<gg, 256>>>(x,  Wk, kb, MROWS, Cc, Cc);
    sgemm_tn<<<gg, 256>>>(x,  Wv, vb, MROWS, Cc, Cc);

    flash_attn<<<dim3(STt / 64, Hh, Bz), 256, smem>>>(qb, kb, vb, yb);

    sgemm_tn<<<gg, 256>>>(yb, Wc, out, MROWS, Cc, Cc);
}

// round 3
// speedup vs baseline: 1.2926x; 1.2926x over previous
#include <cuda_runtime.h>
#include <cuda_bf16.h>
#include <math.h>
#include <stdint.h>

#define Bz  4
#define Tt  2048
#define STt 2048
#define Cc  1024
#define Hh  16
#define Dd  64
#define MROWS (Bz * STt)   // 8192
#define GK 1024

// ---------------- scratch (static device arrays: allocation-guard-safe) ----
__device__ float g_q[(size_t)MROWS * Cc];
__device__ float g_k[(size_t)MROWS * Cc];
__device__ float g_v[(size_t)MROWS * Cc];
__device__ float g_y[(size_t)MROWS * Cc];

__device__ __nv_bfloat16 g_xh[(size_t)MROWS * Cc];
__device__ __nv_bfloat16 g_xl[(size_t)MROWS * Cc];
__device__ __nv_bfloat16 g_sxh[(size_t)MROWS * Cc];
__device__ __nv_bfloat16 g_sxl[(size_t)MROWS * Cc];
__device__ __nv_bfloat16 g_yh[(size_t)MROWS * Cc];
__device__ __nv_bfloat16 g_yl[(size_t)MROWS * Cc];
__device__ __nv_bfloat16 g_wqh[(size_t)Cc * Cc], g_wql[(size_t)Cc * Cc];
__device__ __nv_bfloat16 g_wkh[(size_t)Cc * Cc], g_wkl[(size_t)Cc * Cc];
__device__ __nv_bfloat16 g_wvh[(size_t)Cc * Cc], g_wvl[(size_t)Cc * Cc];
__device__ __nv_bfloat16 g_wch[(size_t)Cc * Cc], g_wcl[(size_t)Cc * Cc];

// ---------------- helpers ---------------------------------------------------
__device__ __forceinline__ uint32_t smem_u32(const void* p) {
    uint32_t a;
    asm("{ .reg .u64 t; cvta.to.shared.u64 t, %1; cvt.u32.u64 %0, t; }"
        : "=r"(a) : "l"(p));
    return a;
}

__device__ __forceinline__ void ldsm_x4(uint32_t* r, uint32_t addr) {
    asm volatile("ldmatrix.sync.aligned.m8n8.x4.shared.b16 {%0,%1,%2,%3}, [%4];"
                 : "=r"(r[0]), "=r"(r[1]), "=r"(r[2]), "=r"(r[3]) : "r"(addr));
}

__device__ __forceinline__ void mma16816(float* d, const uint32_t* a, const uint32_t* b) {
    asm volatile("mma.sync.aligned.m16n8k16.row.col.f32.bf16.bf16.f32 "
                 "{%0,%1,%2,%3}, {%4,%5,%6,%7}, {%8,%9}, {%0,%1,%2,%3};"
                 : "+f"(d[0]), "+f"(d[1]), "+f"(d[2]), "+f"(d[3])
                 : "r"(a[0]), "r"(a[1]), "r"(a[2]), "r"(a[3]), "r"(b[0]), "r"(b[1]));
}

// ---------------------------------------------------------------------------
// fp32 -> (hi, lo) bf16 split
// ---------------------------------------------------------------------------
__global__ void split_kernel(const float* __restrict__ s,
                             __nv_bfloat16* __restrict__ hi,
                             __nv_bfloat16* __restrict__ lo, int n4)
{
    int i = blockIdx.x * blockDim.x + threadIdx.x;
    if (i >= n4) return;
    float4 v = ((const float4*)s)[i];
    float f[4] = {v.x, v.y, v.z, v.w};
    __nv_bfloat162 h2[2], l2[2];
    #pragma unroll
    for (int j = 0; j < 2; j++) {
        __nv_bfloat16 ha = __float2bfloat16(f[2*j]);
        __nv_bfloat16 hb = __float2bfloat16(f[2*j+1]);
        __nv_bfloat16 la = __float2bfloat16(f[2*j]   - __bfloat162float(ha));
        __nv_bfloat16 lb = __float2bfloat16(f[2*j+1] - __bfloat162float(hb));
        h2[j] = __nv_bfloat162(ha, hb);
        l2[j] = __nv_bfloat162(la, lb);
    }
    __nv_bfloat162* hp = (__nv_bfloat162*)hi;
    __nv_bfloat162* lp = (__nv_bfloat162*)lo;
    hp[2*i] = h2[0]; hp[2*i+1] = h2[1];
    lp[2*i] = l2[0]; lp[2*i+1] = l2[1];
}

// ---------------------------------------------------------------------------
// mma.sync bf16x3 GEMM: Out[M,1024] = A[M,1024] @ W[1024,1024]^T  (fp32-accurate)
// CTA 128x128, BK=32, 8 warps (4m x 2n), warp tile 32x64, cp.async double buffer.
// D = Ah.Wh + Ah.Wl + Al.Wh
// ---------------------------------------------------------------------------
#define BM 128
#define BN 128
#define BK 32
#define NST (GK / BK)              // 32 stages
#define PADE 40                    // padded row length (elems)
#define ROWB (PADE * 2)            // 80 bytes/row
#define MAT_BYTES (128 * ROWB)     // 10240
#define STAGE_BYTES (4 * MAT_BYTES)  // 40960 (Ah, Al, Wh, Wl)
#define GEMM_SMEM (2 * STAGE_BYTES)  // 81920

__global__ __launch_bounds__(256, 2)
void gemm_mma_bf16x3(const __nv_bfloat16* __restrict__ Ah,
                     const __nv_bfloat16* __restrict__ Al,
                     const __nv_bfloat16* __restrict__ Wh,
                     const __nv_bfloat16* __restrict__ Wl,
                     float* __restrict__ Out)
{
    extern __shared__ char dsm[];
    const uint32_t sb = smem_u32(dsm);

    const int tid = threadIdx.x;
    const int wid = tid >> 5, lid = tid & 31;
    const int wm = wid & 3, wn = wid >> 2;
    const int m0 = blockIdx.y * BM, n0 = blockIdx.x * BN;

    // ---- loader mapping: 4 groups of 64 threads, one matrix each ----------
    const int lmm = tid >> 6;
    const int l64 = tid & 63;
    const __nv_bfloat16* lg = (lmm == 0) ? Ah : (lmm == 1) ? Al : (lmm == 2) ? Wh : Wl;
    const int lr0 = (lmm < 2) ? m0 : n0;
    const uint32_t lsm = (uint32_t)lmm * MAT_BYTES;

    float acc[2][8][4];
    #pragma unroll
    for (int a = 0; a < 2; a++)
        #pragma unroll
        for (int b = 0; b < 8; b++)
            #pragma unroll
            for (int c = 0; c < 4; c++) acc[a][b][c] = 0.f;

    // per-thread invariant smem offsets for ldmatrix lanes
    const uint32_t aOff = (uint32_t)(wm * 32 + (lid & 15)) * ROWB + ((lid >> 4) * 8) * 2;
    const uint32_t bOff = 2u * MAT_BYTES
        + (uint32_t)(wn * 64 + ((lid >> 4) & 1) * 8 + (lid & 7)) * ROWB
        + (((lid >> 3) & 1) * 8) * 2;

    #define ISSUE_STAGE(t, buf) do {                                              \
        uint32_t base_ = sb + (uint32_t)(buf) * STAGE_BYTES + lsm;                 \
        const __nv_bfloat16* gp0_ = lg + (size_t)lr0 * GK + (t) * BK;              \
        _Pragma("unroll")                                                          \
        for (int p_ = 0; p_ < 8; p_++) {                                           \
            int i_ = p_ * 64 + l64;                                                \
            int row_ = i_ >> 2, vec_ = i_ & 3;                                     \
            const void* gp_ = gp0_ + (size_t)row_ * GK + vec_ * 8;                 \
            uint32_t sp_ = base_ + (uint32_t)(row_ * ROWB + vec_ * 16);            \
            asm volatile("cp.async.cg.shared.global [%0], [%1], 16;"               \
                         :: "r"(sp_), "l"(gp_));                                   \
        }                                                                          \
        asm volatile("cp.async.commit_group;" ::: "memory");                       \
    } while (0)

    ISSUE_STAGE(0, 0);

    for (int t = 0; t < NST; t++) {
        if (t + 1 < NST) {
            ISSUE_STAGE(t + 1, (t + 1) & 1);
            asm volatile("cp.async.wait_group 1;" ::: "memory");
        } else {
            asm volatile("cp.async.wait_group 0;" ::: "memory");
        }
        __syncthreads();

        const uint32_t st = sb + (uint32_t)(t & 1) * STAGE_BYTES;
        #pragma unroll
        for (int kk = 0; kk < 2; kk++) {
            const uint32_t ab = st + aOff + kk * 32;
            uint32_t ah0[4], ah1[4], al0[4], al1[4];
            ldsm_x4(ah0, ab);
            ldsm_x4(ah1, ab + 16 * ROWB);
            ldsm_x4(al0, ab + MAT_BYTES);
            ldsm_x4(al1, ab + MAT_BYTES + 16 * ROWB);

            const uint32_t bb = st + bOff + kk * 32;
            #pragma unroll
            for (int p = 0; p < 4; p++) {
                uint32_t bh[4], bl[4];
                ldsm_x4(bh, bb + p * 16 * ROWB);
                ldsm_x4(bl, bb + p * 16 * ROWB + MAT_BYTES);
                #pragma unroll
                for (int q = 0; q < 2; q++) {
                    mma16816(acc[0][p * 2 + q], ah0, bh + q * 2);
                    mma16816(acc[1][p * 2 + q], ah1, bh + q * 2);
                    mma16816(acc[0][p * 2 + q], ah0, bl + q * 2);
                    mma16816(acc[1][p * 2 + q], ah1, bl + q * 2);
                    mma16816(acc[0][p * 2 + q], al0, bh + q * 2);
                    mma16816(acc[1][p * 2 + q], al1, bh + q * 2);
                }
            }
        }
        __syncthreads();
    }

    // ---- epilogue: fp32 accum -> Out ---------------------------------------
    const int erow = m0 + wm * 32 + (lid >> 2);
    const int ecol = n0 + wn * 64 + (lid & 3) * 2;
    #pragma unroll
    for (int mt = 0; mt < 2; mt++)
        #pragma unroll
        for (int nt = 0; nt < 8; nt++) {
            float2 v0 = make_float2(acc[mt][nt][0], acc[mt][nt][1]);
            float2 v1 = make_float2(acc[mt][nt][2], acc[mt][nt][3]);
            *(float2*)(Out + (size_t)(erow + mt * 16) * Cc + ecol + nt * 8) = v0;
            *(float2*)(Out + (size_t)(erow + mt * 16 + 8) * Cc + ecol + nt * 8) = v1;
        }
}

// ---------------------------------------------------------------------------
// Flash attention (SIMT fp32, 64 q-rows x 64 kv tiles) — unchanged
// ---------------------------------------------------------------------------
#define SM_Q 0
#define SM_K (64 * 65)
#define SM_V (2 * 64 * 65)
#define SM_P (2 * 64 * 65 + 64 * 68)
#define SMEM_FLOATS (2 * 64 * 65 + 2 * 64 * 68)

__global__ __launch_bounds__(256, 2)
void flash_attn(const float* __restrict__ q, const float* __restrict__ k,
                const float* __restrict__ v, float* __restrict__ y)
{
    extern __shared__ float sm[];
    float* Qs = sm + SM_Q;
    float* Ks = sm + SM_K;
    float* Vs = sm + SM_V;
    float* Ps = sm + SM_P;

    const int tid = threadIdx.x;
    const int tx  = tid & 15;
    const int ty  = tid >> 4;
    const int i0  = blockIdx.x * 64;
    const int h   = blockIdx.y;
    const int b   = blockIdx.z;

    const float* qb = q + ((size_t)b * STt + i0) * Cc + h * Dd;
    const float* kb = k + (size_t)b * Tt * Cc + h * Dd;
    const float* vb = v + (size_t)b * Tt * Cc + h * Dd;

    const int ld = tid & 15;
    const int lr = tid >> 4;

    #pragma unroll
    for (int g = 0; g < 4; g++) {
        const int i = lr + g * 16;
        float4 t4 = *(const float4*)(qb + (size_t)i * Cc + ld * 4);
        float* dst = Qs + i * 65 + ld * 4;
        dst[0] = t4.x; dst[1] = t4.y; dst[2] = t4.z; dst[3] = t4.w;
    }

    float m[4], l[4], o[4][4];
    #pragma unroll
    for (int ii = 0; ii < 4; ii++) {
        m[ii] = -1e30f; l[ii] = 0.f;
        #pragma unroll
        for (int cc = 0; cc < 4; cc++) o[ii][cc] = 0.f;
    }

    for (int jt = 0; jt < Tt / 64; jt++) {
        __syncthreads();
        #pragma unroll
        for (int g = 0; g < 4; g++) {
            const int j = lr + g * 16;
            const size_t go = (size_t)(jt * 64 + j) * Cc + ld * 4;
            float4 k4 = *(const float4*)(kb + go);
            float* kd = Ks + j * 65 + ld * 4;
            kd[0] = k4.x; kd[1] = k4.y; kd[2] = k4.z; kd[3] = k4.w;
            float4 v4 = *(const float4*)(vb + go);
            *(float4*)(Vs + j * 68 + ld * 4) = v4;
        }
        __syncthreads();

        float s[4][4];
        #pragma unroll
        for (int ii = 0; ii < 4; ii++)
            #pragma unroll
            for (int jj = 0; jj < 4; jj++) s[ii][jj] = 0.f;

        const float* qrow = Qs + (ty * 4) * 65;
        const float* krow = Ks + (tx * 4) * 65;
        #pragma unroll 4
        for (int d = 0; d < 64; d++) {
            float qf[4], kf[4];
            #pragma unroll
            for (int ii = 0; ii < 4; ii++) qf[ii] = qrow[ii * 65 + d];
            #pragma unroll
            for (int jj = 0; jj < 4; jj++) kf[jj] = krow[jj * 65 + d];
            #pragma unroll
            for (int ii = 0; ii < 4; ii++)
                #pragma unroll
                for (int jj = 0; jj < 4; jj++)
                    s[ii][jj] += qf[ii] * kf[jj];
        }

        #pragma unroll
        for (int ii = 0; ii < 4; ii++) {
            float mm = fmaxf(fmaxf(s[ii][0], s[ii][1]), fmaxf(s[ii][2], s[ii][3]));
            #pragma unroll
            for (int off = 8; off; off >>= 1)
                mm = fmaxf(mm, __shfl_xor_sync(0xffffffffu, mm, off));
            const float mn = fmaxf(m[ii], mm);
            const float sc = __expf(m[ii] - mn);
            m[ii] = mn;
            float ss = 0.f;
            #pragma unroll
            for (int jj = 0; jj < 4; jj++) {
                s[ii][jj] = __expf(s[ii][jj] - mn);
                ss += s[ii][jj];
            }
            #pragma unroll
            for (int off = 8; off; off >>= 1)
                ss += __shfl_xor_sync(0xffffffffu, ss, off);
            l[ii] = l[ii] * sc + ss;
            #pragma unroll
            for (int cc = 0; cc < 4; cc++) o[ii][cc] *= sc;
            *(float4*)(Ps + (ty * 4 + ii) * 68 + tx * 4) =
                make_float4(s[ii][0], s[ii][1], s[ii][2], s[ii][3]);
        }
        __syncthreads();

        const float* prow = Ps + (ty * 4) * 68;
        #pragma unroll 4
        for (int j = 0; j < 64; j++) {
            float pv[4];
            #pragma unroll
            for (int ii = 0; ii < 4; ii++) pv[ii] = prow[ii * 68 + j];
            float4 v4 = *(const float4*)(Vs + j * 68 + tx * 4);
            #pragma unroll
            for (int ii = 0; ii < 4; ii++) {
                o[ii][0] += pv[ii] * v4.x;
                o[ii][1] += pv[ii] * v4.y;
                o[ii][2] += pv[ii] * v4.z;
                o[ii][3] += pv[ii] * v4.w;
            }
        }
    }

    #pragma unroll
    for (int ii = 0; ii < 4; ii++) {
        const float inv = 1.0f / l[ii];
        const int row = i0 + ty * 4 + ii;
        float4 r4 = make_float4(o[ii][0] * inv, o[ii][1] * inv,
                                o[ii][2] * inv, o[ii][3] * inv);
        *(float4*)(y + ((size_t)b * STt + row) * Cc + h * Dd + tx * 4) = r4;
    }
}

// ---------------------------------------------------------------------------
extern "C" void kernel_launch(void* const* d_in, const int* in_sizes, int n_in,
                              void* d_out, int out_size)
{
    const float* x  = (const float*)d_in[0];
    const float* sx = (const float*)d_in[1];
    const float* Wq = (const float*)d_in[2];
    const float* Wk = (const float*)d_in[3];
    const float* Wv = (const float*)d_in[4];
    const float* Wc = (const float*)d_in[5];
    float* out = (float*)d_out;

    float *qb, *kb, *vb, *yb;
    cudaGetSymbolAddress((void**)&qb, g_q);
    cudaGetSymbolAddress((void**)&kb, g_k);
    cudaGetSymbolAddress((void**)&vb, g_v);
    cudaGetSymbolAddress((void**)&yb, g_y);

    __nv_bfloat16 *xh, *xl, *sxh, *sxl, *yh, *yl;
    __nv_bfloat16 *wqh, *wql, *wkh, *wkl, *wvh, *wvl, *wch, *wcl;
    cudaGetSymbolAddress((void**)&xh,  g_xh);  cudaGetSymbolAddress((void**)&xl,  g_xl);
    cudaGetSymbolAddress((void**)&sxh, g_sxh); cudaGetSymbolAddress((void**)&sxl, g_sxl);
    cudaGetSymbolAddress((void**)&yh,  g_yh);  cudaGetSymbolAddress((void**)&yl,  g_yl);
    cudaGetSymbolAddress((void**)&wqh, g_wqh); cudaGetSymbolAddress((void**)&wql, g_wql);
    cudaGetSymbolAddress((void**)&wkh, g_wkh); cudaGetSymbolAddress((void**)&wkl, g_wkl);
    cudaGetSymbolAddress((void**)&wvh, g_wvh); cudaGetSymbolAddress((void**)&wvl, g_wvl);
    cudaGetSymbolAddress((void**)&wch, g_wch); cudaGetSymbolAddress((void**)&wcl, g_wcl);

    const int fsmem = SMEM_FLOATS * (int)sizeof(float);
    cudaFuncSetAttribute(flash_attn, cudaFuncAttributeMaxDynamicSharedMemorySize, fsmem);
    cudaFuncSetAttribute(gemm_mma_bf16x3, cudaFuncAttributeMaxDynamicSharedMemorySize, GEMM_SMEM);

    const int nbig = (MROWS * Cc) / 4;
    const int nwt  = (Cc * Cc) / 4;

    split_kernel<<<(nbig + 255) / 256, 256>>>(sx, sxh, sxl, nbig);
    split_kernel<<<(nbig + 255) / 256, 256>>>(x,  xh,  xl,  nbig);
    split_kernel<<<(nwt + 255) / 256, 256>>>(Wq, wqh, wql, nwt);
    split_kernel<<<(nwt + 255) / 256, 256>>>(Wk, wkh, wkl, nwt);
    split_kernel<<<(nwt + 255) / 256, 256>>>(Wv, wvh, wvl, nwt);
    split_kernel<<<(nwt + 255) / 256, 256>>>(Wc, wch, wcl, nwt);

    dim3 gg(Cc / BN, MROWS / BM);   // (8, 64)
    gemm_mma_bf16x3<<<gg, 256, GEMM_SMEM>>>(sxh, sxl, wqh, wql, qb);
    gemm_mma_bf16x3<<<gg, 256, GEMM_SMEM>>>(xh,  xl,  wkh, wkl, kb);
    gemm_mma_bf16x3<<<gg, 256, GEMM_SMEM>>>(xh,  xl,  wvh, wvl, vb);

    flash_attn<<<dim3(STt / 64, Hh, Bz), 256, fsmem>>>(qb, kb, vb, yb);

    split_kernel<<<(nbig + 255) / 256, 256>>>(yb, yh, yl, nbig);
    gemm_mma_bf16x3<<<gg, 256, GEMM_SMEM>>>(yh, yl, wch, wcl, out);
}

// round 4
// speedup vs baseline: 2.7612x; 2.1361x over previous
#include <cuda_runtime.h>
#include <cuda_bf16.h>
#include <math.h>
#include <stdint.h>

#define Bz  4
#define Tt  2048
#define STt 2048
#define Cc  1024
#define Hh  16
#define Dd  64
#define MROWS (Bz * STt)   // 8192
#define GK 1024

// ---------------- scratch (static device arrays) ---------------------------
__device__ __nv_bfloat16 g_xh[(size_t)MROWS * Cc];
__device__ __nv_bfloat16 g_xl[(size_t)MROWS * Cc];
__device__ __nv_bfloat16 g_sxh[(size_t)MROWS * Cc];
__device__ __nv_bfloat16 g_sxl[(size_t)MROWS * Cc];
__device__ __nv_bfloat16 g_yh[(size_t)MROWS * Cc];
__device__ __nv_bfloat16 g_yl[(size_t)MROWS * Cc];
__device__ __nv_bfloat16 g_qh[(size_t)MROWS * Cc], g_ql[(size_t)MROWS * Cc];
__device__ __nv_bfloat16 g_kh[(size_t)MROWS * Cc], g_kl[(size_t)MROWS * Cc];
__device__ __nv_bfloat16 g_vh[(size_t)MROWS * Cc], g_vl[(size_t)MROWS * Cc];
__device__ __nv_bfloat16 g_wqh[(size_t)Cc * Cc], g_wql[(size_t)Cc * Cc];
__device__ __nv_bfloat16 g_wkh[(size_t)Cc * Cc], g_wkl[(size_t)Cc * Cc];
__device__ __nv_bfloat16 g_wvh[(size_t)Cc * Cc], g_wvl[(size_t)Cc * Cc];
__device__ __nv_bfloat16 g_wch[(size_t)Cc * Cc], g_wcl[(size_t)Cc * Cc];

// ---------------- helpers ---------------------------------------------------
__device__ __forceinline__ uint32_t smem_u32(const void* p) {
    uint32_t a;
    asm("{ .reg .u64 t; cvta.to.shared.u64 t, %1; cvt.u32.u64 %0, t; }"
        : "=r"(a) : "l"(p));
    return a;
}
__device__ __forceinline__ void ldsm_x4(uint32_t* r, uint32_t addr) {
    asm volatile("ldmatrix.sync.aligned.m8n8.x4.shared.b16 {%0,%1,%2,%3}, [%4];"
                 : "=r"(r[0]), "=r"(r[1]), "=r"(r[2]), "=r"(r[3]) : "r"(addr));
}
__device__ __forceinline__ void ldsm_x4_t(uint32_t* r, uint32_t addr) {
    asm volatile("ldmatrix.sync.aligned.m8n8.x4.trans.shared.b16 {%0,%1,%2,%3}, [%4];"
                 : "=r"(r[0]), "=r"(r[1]), "=r"(r[2]), "=r"(r[3]) : "r"(addr));
}
__device__ __forceinline__ void mma16816(float* d, const uint32_t* a, const uint32_t* b) {
    asm volatile("mma.sync.aligned.m16n8k16.row.col.f32.bf16.bf16.f32 "
                 "{%0,%1,%2,%3}, {%4,%5,%6,%7}, {%8,%9}, {%0,%1,%2,%3};"
                 : "+f"(d[0]), "+f"(d[1]), "+f"(d[2]), "+f"(d[3])
                 : "r"(a[0]), "r"(a[1]), "r"(a[2]), "r"(a[3]), "r"(b[0]), "r"(b[1]));
}
// pack two fp32 -> bf16x2 (lo in low half)
__device__ __forceinline__ uint32_t pack_bf16x2(float lo, float hi) {
    uint32_t r;
    asm("cvt.rn.bf16x2.f32 %0, %1, %2;" : "=r"(r) : "f"(hi), "f"(lo));
    return r;
}

// ---------------------------------------------------------------------------
// fp32 -> (hi, lo) bf16 split
// ---------------------------------------------------------------------------
__global__ void split_kernel(const float* __restrict__ s,
                             __nv_bfloat16* __restrict__ hi,
                             __nv_bfloat16* __restrict__ lo, int n4)
{
    int i = blockIdx.x * blockDim.x + threadIdx.x;
    if (i >= n4) return;
    float4 v = ((const float4*)s)[i];
    float f[4] = {v.x, v.y, v.z, v.w};
    __nv_bfloat162 h2[2], l2[2];
    #pragma unroll
    for (int j = 0; j < 2; j++) {
        __nv_bfloat16 ha = __float2bfloat16(f[2*j]);
        __nv_bfloat16 hb = __float2bfloat16(f[2*j+1]);
        __nv_bfloat16 la = __float2bfloat16(f[2*j]   - __bfloat162float(ha));
        __nv_bfloat16 lb = __float2bfloat16(f[2*j+1] - __bfloat162float(hb));
        h2[j] = __nv_bfloat162(ha, hb);
        l2[j] = __nv_bfloat162(la, lb);
    }
    __nv_bfloat162* hp = (__nv_bfloat162*)hi;
    __nv_bfloat162* lp = (__nv_bfloat162*)lo;
    hp[2*i] = h2[0]; hp[2*i+1] = h2[1];
    lp[2*i] = l2[0]; lp[2*i+1] = l2[1];
}

// ---------------------------------------------------------------------------
// mma.sync bf16x3 GEMM: Out = A[M,1024] @ W[1024,1024]^T  (fp32-accurate)
// Epilogue: fp32 OR bf16 hi/lo split (for q/k/v feeding the flash kernel).
// ---------------------------------------------------------------------------
#define BM 128
#define BN 128
#define BK 32
#define NST (GK / BK)
#define PADE 40
#define ROWB (PADE * 2)              // 80 B/row
#define MAT_BYTES (128 * ROWB)       // 10240
#define STAGE_BYTES (4 * MAT_BYTES)  // 40960
#define GEMM_SMEM (2 * STAGE_BYTES)  // 81920

__global__ __launch_bounds__(256, 2)
void gemm_mma_bf16x3(const __nv_bfloat16* __restrict__ Ah,
                     const __nv_bfloat16* __restrict__ Al,
                     const __nv_bfloat16* __restrict__ Wh,
                     const __nv_bfloat16* __restrict__ Wl,
                     float* __restrict__ OutF,
                     __nv_bfloat16* __restrict__ OutH,
                     __nv_bfloat16* __restrict__ OutL)
{
    extern __shared__ char dsm[];
    const uint32_t sb = smem_u32(dsm);

    const int tid = threadIdx.x;
    const int wid = tid >> 5, lid = tid & 31;
    const int wm = wid & 3, wn = wid >> 2;
    const int m0 = blockIdx.y * BM, n0 = blockIdx.x * BN;

    const int lmm = tid >> 6;
    const int l64 = tid & 63;
    const __nv_bfloat16* lg = (lmm == 0) ? Ah : (lmm == 1) ? Al : (lmm == 2) ? Wh : Wl;
    const int lr0 = (lmm < 2) ? m0 : n0;
    const uint32_t lsm = (uint32_t)lmm * MAT_BYTES;

    float acc[2][8][4];
    #pragma unroll
    for (int a = 0; a < 2; a++)
        #pragma unroll
        for (int b = 0; b < 8; b++)
            #pragma unroll
            for (int c = 0; c < 4; c++) acc[a][b][c] = 0.f;

    const uint32_t aOff = (uint32_t)(wm * 32 + (lid & 15)) * ROWB + ((lid >> 4) * 8) * 2;
    const uint32_t bOff = 2u * MAT_BYTES
        + (uint32_t)(wn * 64 + ((lid >> 4) & 1) * 8 + (lid & 7)) * ROWB
        + (((lid >> 3) & 1) * 8) * 2;

    #define ISSUE_STAGE(t, buf) do {                                              \
        uint32_t base_ = sb + (uint32_t)(buf) * STAGE_BYTES + lsm;                 \
        const __nv_bfloat16* gp0_ = lg + (size_t)lr0 * GK + (t) * BK;              \
        _Pragma("unroll")                                                          \
        for (int p_ = 0; p_ < 8; p_++) {                                           \
            int i_ = p_ * 64 + l64;                                                \
            int row_ = i_ >> 2, vec_ = i_ & 3;                                     \
            const void* gp_ = gp0_ + (size_t)row_ * GK + vec_ * 8;                 \
            uint32_t sp_ = base_ + (uint32_t)(row_ * ROWB + vec_ * 16);            \
            asm volatile("cp.async.cg.shared.global [%0], [%1], 16;"               \
                         :: "r"(sp_), "l"(gp_));                                   \
        }                                                                          \
        asm volatile("cp.async.commit_group;" ::: "memory");                       \
    } while (0)

    ISSUE_STAGE(0, 0);

    for (int t = 0; t < NST; t++) {
        if (t + 1 < NST) {
            ISSUE_STAGE(t + 1, (t + 1) & 1);
            asm volatile("cp.async.wait_group 1;" ::: "memory");
        } else {
            asm volatile("cp.async.wait_group 0;" ::: "memory");
        }
        __syncthreads();

        const uint32_t st = sb + (uint32_t)(t & 1) * STAGE_BYTES;
        #pragma unroll
        for (int kk = 0; kk < 2; kk++) {
            const uint32_t ab = st + aOff + kk * 32;
            uint32_t ah0[4], ah1[4], al0[4], al1[4];
            ldsm_x4(ah0, ab);
            ldsm_x4(ah1, ab + 16 * ROWB);
            ldsm_x4(al0, ab + MAT_BYTES);
            ldsm_x4(al1, ab + MAT_BYTES + 16 * ROWB);

            const uint32_t bb = st + bOff + kk * 32;
            #pragma unroll
            for (int p = 0; p < 4; p++) {
                uint32_t bh[4], bl[4];
                ldsm_x4(bh, bb + p * 16 * ROWB);
                ldsm_x4(bl, bb + p * 16 * ROWB + MAT_BYTES);
                #pragma unroll
                for (int q = 0; q < 2; q++) {
                    mma16816(acc[0][p * 2 + q], ah0, bh + q * 2);
                    mma16816(acc[1][p * 2 + q], ah1, bh + q * 2);
                    mma16816(acc[0][p * 2 + q], ah0, bl + q * 2);
                    mma16816(acc[1][p * 2 + q], ah1, bl + q * 2);
                    mma16816(acc[0][p * 2 + q], al0, bh + q * 2);
                    mma16816(acc[1][p * 2 + q], al1, bh + q * 2);
                }
            }
        }
        __syncthreads();
    }
    #undef ISSUE_STAGE

    const int erow = m0 + wm * 32 + (lid >> 2);
    const int ecol = n0 + wn * 64 + (lid & 3) * 2;
    if (OutF) {
        #pragma unroll
        for (int mt = 0; mt < 2; mt++)
            #pragma unroll
            for (int nt = 0; nt < 8; nt++) {
                *(float2*)(OutF + (size_t)(erow + mt * 16) * Cc + ecol + nt * 8) =
                    make_float2(acc[mt][nt][0], acc[mt][nt][1]);
                *(float2*)(OutF + (size_t)(erow + mt * 16 + 8) * Cc + ecol + nt * 8) =
                    make_float2(acc[mt][nt][2], acc[mt][nt][3]);
            }
    } else {
        #pragma unroll
        for (int mt = 0; mt < 2; mt++)
            #pragma unroll
            for (int nt = 0; nt < 8; nt++) {
                #pragma unroll
                for (int rr = 0; rr < 2; rr++) {
                    float f0 = acc[mt][nt][rr * 2], f1 = acc[mt][nt][rr * 2 + 1];
                    __nv_bfloat16 h0 = __float2bfloat16(f0);
                    __nv_bfloat16 h1 = __float2bfloat16(f1);
                    float r0 = f0 - __bfloat162float(h0);
                    float r1 = f1 - __bfloat162float(h1);
                    size_t idx = (size_t)(erow + mt * 16 + rr * 8) * Cc + ecol + nt * 8;
                    *(__nv_bfloat162*)(OutH + idx) = __nv_bfloat162(h0, h1);
                    *(__nv_bfloat162*)(OutL + idx) =
                        __nv_bfloat162(__float2bfloat16(r0), __float2bfloat16(r1));
                }
            }
    }
}

// ---------------------------------------------------------------------------
// Flash attention on mma.sync bf16x3.
// CTA: 128 q-rows x one head. 8 warps x 16 q-rows. KV tiles of 64, double buf.
// ---------------------------------------------------------------------------
#define KROWB 144                   // 64 bf16 = 128 B + 16 pad
#define KMAT  (64 * KROWB)          // 9216
#define KVSTAGE (4 * KMAT)          // 36864 (Kh, Kl, Vh, Vl)
#define QMAT  (128 * KROWB)         // 18432
#define QOFF  (2 * KVSTAGE)         // 73728
#define FLASH_SMEM (QOFF + 2 * QMAT)  // 110592
#define NKV (Tt / 64)               // 32

__global__ __launch_bounds__(256)
void flash_mma(const __nv_bfloat16* __restrict__ qh, const __nv_bfloat16* __restrict__ ql,
               const __nv_bfloat16* __restrict__ kh, const __nv_bfloat16* __restrict__ kl,
               const __nv_bfloat16* __restrict__ vh, const __nv_bfloat16* __restrict__ vl,
               __nv_bfloat16* __restrict__ yh, __nv_bfloat16* __restrict__ yl)
{
    extern __shared__ char dsm[];
    const uint32_t sb = smem_u32(dsm);

    const int tid = threadIdx.x;
    const int wid = tid >> 5, lid = tid & 31;
    const int i0 = blockIdx.x * 128;          // q-row tile within ST
    const int h  = blockIdx.y;
    const int b  = blockIdx.z;

    // ---- Q load: 2 mats x 128 rows x 8 chunks = 2048 cp.async (8/thread) ---
    {
        const int qm = tid >> 7;              // 0: hi, 1: lo
        const int l128 = tid & 127;
        const __nv_bfloat16* qg = (qm == 0) ? qh : ql;
        const uint32_t qsm = sb + QOFF + (uint32_t)qm * QMAT;
        #pragma unroll
        for (int it = 0; it < 8; it++) {
            int idx = it * 128 + l128;
            int row = idx >> 3, ch = idx & 7;
            const void* gp = qg + ((size_t)(b * STt + i0 + row)) * Cc + h * Dd + ch * 8;
            uint32_t sp = qsm + (uint32_t)(row * KROWB + ch * 16);
            asm volatile("cp.async.cg.shared.global [%0], [%1], 16;" :: "r"(sp), "l"(gp));
        }
        asm volatile("cp.async.commit_group;" ::: "memory");
    }

    // ---- KV stage loader ---------------------------------------------------
    const int lmm = tid >> 6;                  // 0:Kh 1:Kl 2:Vh 3:Vl
    const int l64 = tid & 63;
    const __nv_bfloat16* lg = (lmm == 0) ? kh : (lmm == 1) ? kl : (lmm == 2) ? vh : vl;
    const uint32_t lsm = (uint32_t)lmm * KMAT;

    #define ISSUE_KV(jt, buf) do {                                                 \
        uint32_t base_ = sb + (uint32_t)(buf) * KVSTAGE + lsm;                      \
        const __nv_bfloat16* gp0_ = lg + ((size_t)(b * Tt + (jt) * 64)) * Cc + h * Dd; \
        _Pragma("unroll")                                                           \
        for (int p_ = 0; p_ < 8; p_++) {                                            \
            int i_ = p_ * 64 + l64;                                                 \
            int row_ = i_ >> 3, ch_ = i_ & 7;                                       \
            const void* gp_ = gp0_ + (size_t)row_ * Cc + ch_ * 8;                   \
            uint32_t sp_ = base_ + (uint32_t)(row_ * KROWB + ch_ * 16);             \
            asm volatile("cp.async.cg.shared.global [%0], [%1], 16;"                \
                         :: "r"(sp_), "l"(gp_));                                    \
        }                                                                           \
        asm volatile("cp.async.commit_group;" ::: "memory");                        \
    } while (0)

    ISSUE_KV(0, 0);

    // ---- Q fragments (wait for Q group: 2 groups committed, keep <=1) ------
    asm volatile("cp.async.wait_group 1;" ::: "memory");
    __syncthreads();

    uint32_t qhf[4][4], qlf[4][4];
    {
        const uint32_t qOff = sb + QOFF + (uint32_t)(wid * 16 + (lid & 15)) * KROWB
                              + (lid >> 4) * 16;
        #pragma unroll
        for (int kc = 0; kc < 4; kc++) {
            ldsm_x4(qhf[kc], qOff + kc * 32);
            ldsm_x4(qlf[kc], qOff + kc * 32 + QMAT);
        }
    }

    float o[8][4];
    #pragma unroll
    for (int nt = 0; nt < 8; nt++)
        #pragma unroll
        for (int c = 0; c < 4; c++) o[nt][c] = 0.f;
    float m0 = -1e30f, m1 = -1e30f, l0 = 0.f, l1 = 0.f;

    const uint32_t kOffL = (uint32_t)(((lid & 7) + ((lid >> 4) & 1) * 8)) * KROWB
                           + ((lid >> 3) & 1) * 16;
    const uint32_t vOffL = (uint32_t)(lid & 15) * KROWB + (lid >> 4) * 16;

    for (int jt = 0; jt < NKV; jt++) {
        if (jt + 1 < NKV) {
            ISSUE_KV(jt + 1, (jt + 1) & 1);
            asm volatile("cp.async.wait_group 1;" ::: "memory");
        } else {
            asm volatile("cp.async.wait_group 0;" ::: "memory");
        }
        __syncthreads();

        const uint32_t st = sb + (uint32_t)(jt & 1) * KVSTAGE;

        // ---- S = Q K^T (split x3) ------------------------------------------
        float s[8][4];
        #pragma unroll
        for (int nt = 0; nt < 8; nt++)
            #pragma unroll
            for (int c = 0; c < 4; c++) s[nt][c] = 0.f;

        #pragma unroll
        for (int kc = 0; kc < 4; kc++) {
            #pragma unroll
            for (int ng = 0; ng < 4; ng++) {
                uint32_t bh[4], bl[4];
                const uint32_t kb = st + kOffL + (uint32_t)(ng * 16) * KROWB + kc * 32;
                ldsm_x4(bh, kb);
                ldsm_x4(bl, kb + KMAT);
                #pragma unroll
                for (int q = 0; q < 2; q++) {
                    mma16816(s[ng * 2 + q], qhf[kc], bh + q * 2);
                    mma16816(s[ng * 2 + q], qhf[kc], bl + q * 2);
                    mma16816(s[ng * 2 + q], qlf[kc], bh + q * 2);
                }
            }
        }

        // ---- online softmax -------------------------------------------------
        float mt0 = -1e30f, mt1 = -1e30f;
        #pragma unroll
        for (int nt = 0; nt < 8; nt++) {
            mt0 = fmaxf(mt0, fmaxf(s[nt][0], s[nt][1]));
            mt1 = fmaxf(mt1, fmaxf(s[nt][2], s[nt][3]));
        }
        mt0 = fmaxf(mt0, __shfl_xor_sync(0xffffffffu, mt0, 1));
        mt0 = fmaxf(mt0, __shfl_xor_sync(0xffffffffu, mt0, 2));
        mt1 = fmaxf(mt1, __shfl_xor_sync(0xffffffffu, mt1, 1));
        mt1 = fmaxf(mt1, __shfl_xor_sync(0xffffffffu, mt1, 2));
        const float mn0 = fmaxf(m0, mt0), mn1 = fmaxf(m1, mt1);
        const float sc0 = __expf(m0 - mn0), sc1 = __expf(m1 - mn1);
        m0 = mn0; m1 = mn1;

        float ls0 = 0.f, ls1 = 0.f;
        #pragma unroll
        for (int nt = 0; nt < 8; nt++) {
            s[nt][0] = __expf(s[nt][0] - mn0);
            s[nt][1] = __expf(s[nt][1] - mn0);
            s[nt][2] = __expf(s[nt][2] - mn1);
            s[nt][3] = __expf(s[nt][3] - mn1);
            ls0 += s[nt][0] + s[nt][1];
            ls1 += s[nt][2] + s[nt][3];
        }
        ls0 += __shfl_xor_sync(0xffffffffu, ls0, 1);
        ls0 += __shfl_xor_sync(0xffffffffu, ls0, 2);
        ls1 += __shfl_xor_sync(0xffffffffu, ls1, 1);
        ls1 += __shfl_xor_sync(0xffffffffu, ls1, 2);
        l0 = l0 * sc0 + ls0;
        l1 = l1 * sc1 + ls1;

        #pragma unroll
        for (int nt = 0; nt < 8; nt++) {
            o[nt][0] *= sc0; o[nt][1] *= sc0;
            o[nt][2] *= sc1; o[nt][3] *= sc1;
        }

        // ---- P -> bf16 hi/lo A-fragments ------------------------------------
        uint32_t ph[4][4], pl[4][4];
        #pragma unroll
        for (int kc = 0; kc < 4; kc++) {
            #pragma unroll
            for (int half = 0; half < 2; half++) {       // n-tile 2kc + half
                const int nt = kc * 2 + half;
                float f0 = s[nt][0], f1 = s[nt][1], f2 = s[nt][2], f3 = s[nt][3];
                uint32_t h01 = pack_bf16x2(f0, f1);
                uint32_t h23 = pack_bf16x2(f2, f3);
                __nv_bfloat162 hb01 = *(__nv_bfloat162*)&h01;
                __nv_bfloat162 hb23 = *(__nv_bfloat162*)&h23;
                uint32_t l01 = pack_bf16x2(f0 - __bfloat162float(hb01.x),
                                           f1 - __bfloat162float(hb01.y));
                uint32_t l23 = pack_bf16x2(f2 - __bfloat162float(hb23.x),
                                           f3 - __bfloat162float(hb23.y));
                ph[kc][half * 2 + 0] = h01;  // a0/a2: row r
                ph[kc][half * 2 + 1] = h23;  // a1/a3: row r+8
                pl[kc][half * 2 + 0] = l01;
                pl[kc][half * 2 + 1] = l23;
            }
        }

        // ---- O += P V (split x3) --------------------------------------------
        #pragma unroll
        for (int kc = 0; kc < 4; kc++) {
            #pragma unroll
            for (int ng = 0; ng < 4; ng++) {
                uint32_t bvh[4], bvl[4];
                const uint32_t vb = st + 2u * KMAT + vOffL
                                    + (uint32_t)(kc * 16) * KROWB + ng * 32;
                ldsm_x4_t(bvh, vb);
                ldsm_x4_t(bvl, vb + KMAT);
                #pragma unroll
                for (int q = 0; q < 2; q++) {
                    mma16816(o[ng * 2 + q], ph[kc], bvh + q * 2);
                    mma16816(o[ng * 2 + q], ph[kc], bvl + q * 2);
                    mma16816(o[ng * 2 + q], pl[kc], bvh + q * 2);
                }
            }
        }
        __syncthreads();
    }
    #undef ISSUE_KV

    // ---- epilogue: y = O / l, split bf16 hi/lo ------------------------------
    const float inv0 = 1.0f / l0, inv1 = 1.0f / l1;
    const int r = lid >> 2;
    const int cq = (lid & 3) * 2;
    const size_t row0 = ((size_t)(b * STt + i0 + wid * 16 + r)) * Cc + h * Dd;
    const size_t row1 = row0 + 8 * Cc;
    #pragma unroll
    for (int nt = 0; nt < 8; nt++) {
        const int c = cq + nt * 8;
        float f0 = o[nt][0] * inv0, f1 = o[nt][1] * inv0;
        float f2 = o[nt][2] * inv1, f3 = o[nt][3] * inv1;
        __nv_bfloat16 h0 = __float2bfloat16(f0), h1 = __float2bfloat16(f1);
        __nv_bfloat16 h2 = __float2bfloat16(f2), h3 = __float2bfloat16(f3);
        *(__nv_bfloat162*)(yh + row0 + c) = __nv_bfloat162(h0, h1);
        *(__nv_bfloat162*)(yh + row1 + c) = __nv_bfloat162(h2, h3);
        *(__nv_bfloat162*)(yl + row0 + c) =
            __nv_bfloat162(__float2bfloat16(f0 - __bfloat162float(h0)),
                           __float2bfloat16(f1 - __bfloat162float(h1)));
        *(__nv_bfloat162*)(yl + row1 + c) =
            __nv_bfloat162(__float2bfloat16(f2 - __bfloat162float(h2)),
                           __float2bfloat16(f3 - __bfloat162float(h3)));
    }
}

// ---------------------------------------------------------------------------
extern "C" void kernel_launch(void* const* d_in, const int* in_sizes, int n_in,
                              void* d_out, int out_size)
{
    const float* x  = (const float*)d_in[0];
    const float* sx = (const float*)d_in[1];
    const float* Wq = (const float*)d_in[2];
    const float* Wk = (const float*)d_in[3];
    const float* Wv = (const float*)d_in[4];
    const float* Wc = (const float*)d_in[5];
    float* out = (float*)d_out;

    __nv_bfloat16 *xh, *xl, *sxh, *sxl, *yh, *yl;
    __nv_bfloat16 *qh, *ql, *kh, *kl, *vh, *vl;
    __nv_bfloat16 *wqh, *wql, *wkh, *wkl, *wvh, *wvl, *wch, *wcl;
    cudaGetSymbolAddress((void**)&xh,  g_xh);  cudaGetSymbolAddress((void**)&xl,  g_xl);
    cudaGetSymbolAddress((void**)&sxh, g_sxh); cudaGetSymbolAddress((void**)&sxl, g_sxl);
    cudaGetSymbolAddress((void**)&yh,  g_yh);  cudaGetSymbolAddress((void**)&yl,  g_yl);
    cudaGetSymbolAddress((void**)&qh,  g_qh);  cudaGetSymbolAddress((void**)&ql,  g_ql);
    cudaGetSymbolAddress((void**)&kh,  g_kh);  cudaGetSymbolAddress((void**)&kl,  g_kl);
    cudaGetSymbolAddress((void**)&vh,  g_vh);  cudaGetSymbolAddress((void**)&vl,  g_vl);
    cudaGetSymbolAddress((void**)&wqh, g_wqh); cudaGetSymbolAddress((void**)&wql, g_wql);
    cudaGetSymbolAddress((void**)&wkh, g_wkh); cudaGetSymbolAddress((void**)&wkl, g_wkl);
    cudaGetSymbolAddress((void**)&wvh, g_wvh); cudaGetSymbolAddress((void**)&wvl, g_wvl);
    cudaGetSymbolAddress((void**)&wch, g_wch); cudaGetSymbolAddress((void**)&wcl, g_wcl);

    cudaFuncSetAttribute(gemm_mma_bf16x3, cudaFuncAttributeMaxDynamicSharedMemorySize, GEMM_SMEM);
    cudaFuncSetAttribute(flash_mma, cudaFuncAttributeMaxDynamicSharedMemorySize, FLASH_SMEM);

    const int nbig = (MROWS * Cc) / 4;
    const int nwt  = (Cc * Cc) / 4;

    split_kernel<<<(nbig + 255) / 256, 256>>>(sx, sxh, sxl, nbig);
    split_kernel<<<(nbig + 255) / 256, 256>>>(x,  xh,  xl,  nbig);
    split_kernel<<<(nwt + 255) / 256, 256>>>(Wq, wqh, wql, nwt);
    split_kernel<<<(nwt + 255) / 256, 256>>>(Wk, wkh, wkl, nwt);
    split_kernel<<<(nwt + 255) / 256, 256>>>(Wv, wvh, wvl, nwt);
    split_kernel<<<(nwt + 255) / 256, 256>>>(Wc, wch, wcl, nwt);

    dim3 gg(Cc / BN, MROWS / BM);   // (8, 64)
    gemm_mma_bf16x3<<<gg, 256, GEMM_SMEM>>>(sxh, sxl, wqh, wql, nullptr, qh, ql);
    gemm_mma_bf16x3<<<gg, 256, GEMM_SMEM>>>(xh,  xl,  wkh, wkl, nullptr, kh, kl);
    gemm_mma_bf16x3<<<gg, 256, GEMM_SMEM>>>(xh,  xl,  wvh, wvl, nullptr, vh, vl);

    flash_mma<<<dim3(STt / 128, Hh, Bz), 256, FLASH_SMEM>>>(qh, ql, kh, kl, vh, vl, yh, yl);

    gemm_mma_bf16x3<<<gg, 256, GEMM_SMEM>>>(yh, yl, wch, wcl, out, nullptr, nullptr);
}